// round 15
// baseline (speedup 1.0000x reference)
#include <cuda_runtime.h>
#include <cuda_fp16.h>
#include <cstdint>

#define NMAX 100000
#define EMAX 1600000
#define ELLW 64

// ---------------- device scratch ----------------
__device__ int    g_cursor[NMAX];                 // degree counter
__device__ int    g_adj_ell[(size_t)NMAX * ELLW]; // ELL adjacency
__device__ __half g_hA[(size_t)NMAX * 128];
__device__ __half g_hB[(size_t)NMAX * 128];
__device__ __half g_ys[(size_t)NMAX * 128];       // self-path GEMM result (+bias)
__device__ __half g_z[(size_t)NMAX * 128];        // neighbor-path GEMM result
// weight images in m16n8k16 fragment order, fp16: [Ws|Wn] (K=128 x 2*DOUT)
__device__ __half g_wt1[128 * 256];
__device__ __half g_wt2[128 * 128];

__device__ __forceinline__ uint32_t smem_u32(const void* p) {
    uint32_t a;
    asm("{ .reg .u64 t; cvta.to.shared.u64 t, %1; cvt.u32.u64 %0, t; }" : "=r"(a) : "l"(p));
    return a;
}
__device__ __forceinline__ void ldmatrix_x4(uint32_t* r, uint32_t addr) {
    asm volatile("ldmatrix.sync.aligned.m8n8.x4.shared.b16 {%0,%1,%2,%3}, [%4];"
                 : "=r"(r[0]), "=r"(r[1]), "=r"(r[2]), "=r"(r[3]) : "r"(addr));
}
__device__ __forceinline__ void mma16(float* c, const uint32_t* a, const uint32_t* b) {
    asm volatile(
        "mma.sync.aligned.m16n8k16.row.col.f32.f16.f16.f32 "
        "{%0,%1,%2,%3},{%4,%5,%6,%7},{%8,%9},{%0,%1,%2,%3};"
        : "+f"(c[0]), "+f"(c[1]), "+f"(c[2]), "+f"(c[3])
        : "r"(a[0]), "r"(a[1]), "r"(a[2]), "r"(a[3]), "r"(b[0]), "r"(b[1]));
}

// fragment index for B image: element (k, nn) of [K=128 x dout2]
__device__ __forceinline__ int wfrag_idx(int k, int nn, int dout2) {
    int NT2 = dout2 >> 3;
    int ks = k >> 4, nt = nn >> 3;
    int lane = ((nn & 7) << 2) | ((k & 7) >> 1);
    int reg = (k >> 3) & 1;
    return ((((ks * NT2 + nt) * 32 + lane) * 2 + reg) << 1) | (k & 1);
}

// ---------------- ELL build ----------------
__global__ void k_zero(int n) {
    int i = blockIdx.x * blockDim.x + threadIdx.x;
    if (i < n) g_cursor[i] = 0;
}
__global__ void k_fill_ell(const int* __restrict__ src, const int* __restrict__ dst, int e) {
    int i = blockIdx.x * blockDim.x + threadIdx.x;
    if (i < e) {
        int d = dst[i];
        int p = atomicAdd(&g_cursor[d], 1);
        if (p < ELLW) g_adj_ell[(size_t)d * ELLW + p] = src[i];
    }
}

// ---------------- W preprocessing (layers 1,2): fragment order, fp16 ----------------
__global__ void k_prepw(const float* __restrict__ Ws, const float* __restrict__ Wn,
                        __half* __restrict__ o, int dout) {
    int i = blockIdx.x * blockDim.x + threadIdx.x;
    int dout2 = 2 * dout;
    if (i >= 128 * dout2) return;
    int k = i / dout2, nn = i % dout2;
    float v = (nn < dout) ? Ws[k * dout + nn] : Wn[k * dout + nn - dout];
    o[wfrag_idx(k, nn, dout2)] = __float2half(v);
}

// ---------------- shared MMA mainloop + epilogue (A already in Asm) ----------------
template <int DOUT>
__device__ __forceinline__ void mma_and_store(
    const __half* Wsm, const __half* Asm, const float* __restrict__ bias,
    __half* __restrict__ ys, __half* __restrict__ z, int n, int row0,
    int wid, int lane) {
    constexpr int DOUT2 = 2 * DOUT;
    constexpr int NT2 = DOUT2 / 8;
    constexpr int NT = NT2 / 2;
    constexpr int ASTRIDE = 136;

    int wm = wid & 3, wn = wid >> 2;
    float acc[2][NT][4];
#pragma unroll
    for (int i = 0; i < 2; ++i)
#pragma unroll
        for (int j = 0; j < NT; ++j)
#pragma unroll
            for (int q = 0; q < 4; ++q) acc[i][j][q] = 0.f;

    uint32_t abase = smem_u32(Asm);
#pragma unroll
    for (int ks = 0; ks < 8; ++ks) {
        uint32_t af[2][4];
#pragma unroll
        for (int i = 0; i < 2; ++i) {
            int row = (wm * 2 + i) * 16 + (lane & 15);
            int col = ks * 16 + (lane >> 4) * 8;
            ldmatrix_x4(af[i], abase + (row * ASTRIDE + col) * 2);
        }
#pragma unroll
        for (int nt = 0; nt < NT; ++nt) {
            int ntg = wn * NT + nt;
            uint2 b2 = *(const uint2*)(Wsm + ((ks * NT2 + ntg) * 32 + lane) * 4);
            uint32_t bf[2] = {b2.x, b2.y};
            mma16(acc[0][nt], af[0], bf);
            mma16(acc[1][nt], af[1], bf);
        }
    }

    int gp = lane >> 2, tg = lane & 3;
#pragma unroll
    for (int i = 0; i < 2; ++i) {
        int r = row0 + (wm * 2 + i) * 16 + gp;
#pragma unroll
        for (int nt = 0; nt < NT; ++nt) {
            int cc = (wn * NT + nt) * 8 + tg * 2;
            if (wn == 0) {
                float b0 = bias[cc], b1 = bias[cc + 1];
                __half2 p0 = __floats2half2_rn(acc[i][nt][0] + b0, acc[i][nt][1] + b1);
                __half2 p1 = __floats2half2_rn(acc[i][nt][2] + b0, acc[i][nt][3] + b1);
                if (r < n)     *(__half2*)(ys + (size_t)r * DOUT + cc) = p0;
                if (r + 8 < n) *(__half2*)(ys + (size_t)(r + 8) * DOUT + cc) = p1;
            } else {
                int c2 = cc - DOUT;
                __half2 p0 = __floats2half2_rn(acc[i][nt][0], acc[i][nt][1]);
                __half2 p1 = __floats2half2_rn(acc[i][nt][2], acc[i][nt][3]);
                if (r < n)     *(__half2*)(z + (size_t)r * DOUT + c2) = p0;
                if (r + 8 < n) *(__half2*)(z + (size_t)(r + 8) * DOUT + c2) = p1;
            }
        }
    }
}

// ---------------- layer-0 GEMM: persistent tiles, A from fp32 x, W converted in-kernel ----------------
__global__ __launch_bounds__(256, 1)
void k_gemm_f32(const float* __restrict__ X,
                const float* __restrict__ Ws, const float* __restrict__ Wn,
                const float* __restrict__ bias, __half* __restrict__ ys,
                __half* __restrict__ z, int n, int ntiles) {
    constexpr int DOUT = 128;
    constexpr int DOUT2 = 256;
    constexpr int ASTRIDE = 136;
    extern __shared__ __half smh[];
    __half* Wsm = smh;
    __half* Asm = smh + 128 * DOUT2;
    int tid = threadIdx.x, wid = tid >> 5, lane = tid & 31;

    // convert raw fp32 W -> fragment-order fp16 smem (once per CTA)
    for (int i = tid; i < 128 * DOUT2; i += 256) {
        int k = i >> 8, nn = i & 255;
        float v = (nn < DOUT) ? Ws[k * DOUT + nn] : Wn[k * DOUT + nn - DOUT];
        Wsm[wfrag_idx(k, nn, DOUT2)] = __float2half(v);
    }

    for (int t = blockIdx.x; t < ntiles; t += gridDim.x) {
        int row0 = t * 128;
#pragma unroll
        for (int u = 0; u < 8; ++u) {
            int idx = tid + u * 256;
            int r = idx >> 4, c8 = idx & 15;
            int gr = row0 + r;
            uint4 o = {0u, 0u, 0u, 0u};
            if (gr < n) {
                const float4* xr = (const float4*)(X + (size_t)gr * 128 + c8 * 8);
                float4 v0 = xr[0], v1 = xr[1];
                __half2 h0 = __floats2half2_rn(v0.x, v0.y);
                __half2 h1 = __floats2half2_rn(v0.z, v0.w);
                __half2 h2 = __floats2half2_rn(v1.x, v1.y);
                __half2 h3 = __floats2half2_rn(v1.z, v1.w);
                o.x = *(uint32_t*)&h0; o.y = *(uint32_t*)&h1;
                o.z = *(uint32_t*)&h2; o.w = *(uint32_t*)&h3;
            }
            *(uint4*)(Asm + r * ASTRIDE + c8 * 8) = o;
        }
        __syncthreads();
        mma_and_store<DOUT>(Wsm, Asm, bias, ys, z, n, row0, wid, lane);
        __syncthreads();
    }
}

// ---------------- layers 1/2 GEMM: persistent tiles, A from fp16 ----------------
template <int DOUT>
__global__ __launch_bounds__(256, 1)
void k_gemm(const __half* __restrict__ A, const __half* __restrict__ Wimg,
            const float* __restrict__ bias, __half* __restrict__ ys,
            __half* __restrict__ z, int n, int ntiles) {
    constexpr int DOUT2 = 2 * DOUT;
    constexpr int ASTRIDE = 136;
    extern __shared__ __half smh[];
    __half* Wsm = smh;
    __half* Asm = smh + 128 * DOUT2;
    int tid = threadIdx.x, wid = tid >> 5, lane = tid & 31;

    {
        const uint4* g = (const uint4*)Wimg;
        uint4* s = (uint4*)Wsm;
        for (int i = tid; i < 128 * DOUT2 / 8; i += 256) s[i] = g[i];
    }

    for (int t = blockIdx.x; t < ntiles; t += gridDim.x) {
        int row0 = t * 128;
        const uint2* g = (const uint2*)A;
#pragma unroll
        for (int u = 0; u < 16; ++u) {
            int idx = tid + u * 256;
            int r = idx >> 5, c = idx & 31;
            int gr = row0 + r;
            uint2 tt = {0u, 0u};
            if (gr < n) tt = g[(size_t)gr * 32 + c];
            *(uint2*)(Asm + r * ASTRIDE + c * 4) = tt;
        }
        __syncthreads();
        mma_and_store<DOUT>(Wsm, Asm, bias, ys, z, n, row0, wid, lane);
        __syncthreads();
    }
}

// ---------------- combine: persistent grid-stride, warp per node ----------------
template <int DOUT, bool RELU, typename OutT>
__global__ __launch_bounds__(512)
void k_comb(const __half* __restrict__ z, const __half* __restrict__ ys,
            OutT* __restrict__ out, int n) {
    int lane = threadIdx.x & 31;
    int wid = threadIdx.x >> 5;
    int wstride = gridDim.x * 16;

    for (int nid = blockIdx.x * 16 + wid; nid < n; nid += wstride) {
        int deg = g_cursor[nid];
        if (deg > ELLW) deg = ELLW;
        float di = 1.0f / (float)max(deg, 1);
        const int* row = g_adj_ell + (size_t)nid * ELLW;

        if constexpr (DOUT == 128) {
            const uint2* z2 = (const uint2*)z;
            uint2 yv = __ldg((const uint2*)ys + (size_t)nid * 32 + lane);
            float a0 = 0.f, a1 = 0.f, a2 = 0.f, a3 = 0.f;
            int j = 0;
            for (; j + 7 < deg; j += 8) {
                uint2 t[8];
#pragma unroll
                for (int u = 0; u < 8; ++u) t[u] = __ldg(z2 + (size_t)row[j + u] * 32 + lane);
#pragma unroll
                for (int u = 0; u < 8; ++u) {
                    float2 fl = __half22float2(*(const __half2*)&t[u].x);
                    float2 fh = __half22float2(*(const __half2*)&t[u].y);
                    a0 += fl.x; a1 += fl.y; a2 += fh.x; a3 += fh.y;
                }
            }
            for (; j < deg; ++j) {
                uint2 t = __ldg(z2 + (size_t)row[j] * 32 + lane);
                float2 fl = __half22float2(*(const __half2*)&t.x);
                float2 fh = __half22float2(*(const __half2*)&t.y);
                a0 += fl.x; a1 += fl.y; a2 += fh.x; a3 += fh.y;
            }
            float2 yl = __half22float2(*(const __half2*)&yv.x);
            float2 yh = __half22float2(*(const __half2*)&yv.y);
            float f0 = a0 * di + yl.x, f1 = a1 * di + yl.y;
            float f2 = a2 * di + yh.x, f3 = a3 * di + yh.y;
            if (RELU) {
                f0 = fmaxf(f0, 0.f); f1 = fmaxf(f1, 0.f);
                f2 = fmaxf(f2, 0.f); f3 = fmaxf(f3, 0.f);
            }
            __half2 lo = __floats2half2_rn(f0, f1);
            __half2 hi = __floats2half2_rn(f2, f3);
            uint2 o;
            o.x = *(uint32_t*)&lo;
            o.y = *(uint32_t*)&hi;
            ((uint2*)out)[(size_t)nid * 32 + lane] = o;
        } else {
            const uint32_t* z1 = (const uint32_t*)z;
            uint32_t yv = __ldg((const uint32_t*)ys + (size_t)nid * 32 + lane);
            float a0 = 0.f, a1 = 0.f;
            int j = 0;
            for (; j + 7 < deg; j += 8) {
                uint32_t t[8];
#pragma unroll
                for (int u = 0; u < 8; ++u) t[u] = __ldg(z1 + (size_t)row[j + u] * 32 + lane);
#pragma unroll
                for (int u = 0; u < 8; ++u) {
                    float2 f = __half22float2(*(const __half2*)&t[u]);
                    a0 += f.x; a1 += f.y;
                }
            }
            for (; j < deg; ++j) {
                uint32_t t = __ldg(z1 + (size_t)row[j] * 32 + lane);
                float2 f = __half22float2(*(const __half2*)&t);
                a0 += f.x; a1 += f.y;
            }
            float2 yf = __half22float2(*(const __half2*)&yv);
            float2 o;
            o.x = a0 * di + yf.x;
            o.y = a1 * di + yf.y;
            if (RELU) { o.x = fmaxf(o.x, 0.f); o.y = fmaxf(o.y, 0.f); }
            ((float2*)out)[(size_t)nid * 32 + lane] = o;
        }
    }
}

// ---------------- launch ----------------
extern "C" void kernel_launch(void* const* d_in, const int* in_sizes, int n_in,
                              void* d_out, int out_size) {
    const float* x   = (const float*)d_in[0];
    const int*   src = (const int*)d_in[1];
    const int*   dst = (const int*)d_in[2];
    const float* Ws0 = (const float*)d_in[3];
    const float* Wn0 = (const float*)d_in[4];
    const float* b0  = (const float*)d_in[5];
    const float* Ws1 = (const float*)d_in[6];
    const float* Wn1 = (const float*)d_in[7];
    const float* b1  = (const float*)d_in[8];
    const float* Ws2 = (const float*)d_in[9];
    const float* Wn2 = (const float*)d_in[10];
    const float* b2  = (const float*)d_in[11];
    float* out = (float*)d_out;

    int n = in_sizes[0] / 128;
    int e = in_sizes[1];

    __half *hA, *hB, *ys, *z, *wt1, *wt2;
    cudaGetSymbolAddress((void**)&hA,  g_hA);
    cudaGetSymbolAddress((void**)&hB,  g_hB);
    cudaGetSymbolAddress((void**)&ys,  g_ys);
    cudaGetSymbolAddress((void**)&z,   g_z);
    cudaGetSymbolAddress((void**)&wt1, g_wt1);
    cudaGetSymbolAddress((void**)&wt2, g_wt2);

    const int SM128 = (128 * 256 + 128 * 136) * 2;   // 100352
    const int SM64  = (128 * 128 + 128 * 136) * 2;   // 67584
    cudaFuncSetAttribute(k_gemm_f32,
                         cudaFuncAttributeMaxDynamicSharedMemorySize, SM128);
    cudaFuncSetAttribute(k_gemm<128>,
                         cudaFuncAttributeMaxDynamicSharedMemorySize, SM128);
    cudaFuncSetAttribute(k_gemm<64>,
                         cudaFuncAttributeMaxDynamicSharedMemorySize, SM64);

    int nsm = 148;
    cudaDeviceGetAttribute(&nsm, cudaDevAttrMultiProcessorCount, 0);

    int ntiles = (n + 127) / 128;
    int gp = 2 * nsm;                 // persistent gemm grid (2 CTAs/SM)
    if (gp > ntiles) gp = ntiles;
    int gc = 4 * nsm;                 // persistent comb grid (4 x 512thr / SM)

    cudaStream_t s2;
    cudaStreamCreateWithFlags(&s2, cudaStreamNonBlocking);
    cudaEvent_t evFork, evJoin;
    cudaEventCreateWithFlags(&evFork, cudaEventDisableTiming);
    cudaEventCreateWithFlags(&evJoin, cudaEventDisableTiming);

    cudaEventRecord(evFork, 0);
    cudaStreamWaitEvent(s2, evFork, 0);

    // s2: ELL build + wt1/wt2 prep (all overlapped with gemm0)
    k_zero<<<(n + 255) / 256, 256, 0, s2>>>(n);
    k_fill_ell<<<(e + 255) / 256, 256, 0, s2>>>(src, dst, e);
    k_prepw<<<(128 * 256 + 255) / 256, 256, 0, s2>>>(Ws1, Wn1, wt1, 128);
    k_prepw<<<(128 * 128 + 255) / 256, 256, 0, s2>>>(Ws2, Wn2, wt2, 64);
    cudaEventRecord(evJoin, s2);

    // main: gemm0 immediately (converts W0 in-kernel)
    k_gemm_f32<<<gp, 256, SM128>>>(x, Ws0, Wn0, b0, ys, z, n, ntiles);

    cudaStreamWaitEvent(0, evJoin, 0);

    k_comb<128, true, __half><<<gc, 512>>>(z, ys, hA, n);
    k_gemm<128><<<gp, 256, SM128>>>(hA, wt1, b1, ys, z, n, ntiles);
    k_comb<128, true, __half><<<gc, 512>>>(z, ys, hB, n);
    k_gemm<64><<<gp, 256, SM64>>>(hB, wt2, b2, ys, z, n, ntiles);
    k_comb<64, false, float><<<gc, 512>>>(z, ys, out, n);

    cudaEventDestroy(evFork);
    cudaEventDestroy(evJoin);
    cudaStreamDestroy(s2);
}

// round 16
// speedup vs baseline: 1.1110x; 1.1110x over previous
#include <cuda_runtime.h>
#include <cuda_fp16.h>
#include <cstdint>

#define NMAX 100000
#define EMAX 1600000
#define ELLW 64

// ---------------- device scratch ----------------
__device__ int    g_cursor[NMAX];                 // degree counter
__device__ int    g_adj_ell[(size_t)NMAX * ELLW]; // ELL adjacency
__device__ __half g_hA[(size_t)NMAX * 128];
__device__ __half g_hB[(size_t)NMAX * 128];
__device__ __half g_ys[(size_t)NMAX * 128];       // self-path GEMM result (+bias)
__device__ __half g_z[(size_t)NMAX * 128];        // neighbor-path GEMM result
// weight images in m16n8k16 fragment order, fp16: [Ws|Wn] (K=128 x 2*DOUT)
__device__ __half g_wt0[128 * 256];
__device__ __half g_wt1[128 * 256];
__device__ __half g_wt2[128 * 128];

__device__ __forceinline__ uint32_t smem_u32(const void* p) {
    uint32_t a;
    asm("{ .reg .u64 t; cvta.to.shared.u64 t, %1; cvt.u32.u64 %0, t; }" : "=r"(a) : "l"(p));
    return a;
}
__device__ __forceinline__ void ldmatrix_x4(uint32_t* r, uint32_t addr) {
    asm volatile("ldmatrix.sync.aligned.m8n8.x4.shared.b16 {%0,%1,%2,%3}, [%4];"
                 : "=r"(r[0]), "=r"(r[1]), "=r"(r[2]), "=r"(r[3]) : "r"(addr));
}
__device__ __forceinline__ void mma16(float* c, const uint32_t* a, const uint32_t* b) {
    asm volatile(
        "mma.sync.aligned.m16n8k16.row.col.f32.f16.f16.f32 "
        "{%0,%1,%2,%3},{%4,%5,%6,%7},{%8,%9},{%0,%1,%2,%3};"
        : "+f"(c[0]), "+f"(c[1]), "+f"(c[2]), "+f"(c[3])
        : "r"(a[0]), "r"(a[1]), "r"(a[2]), "r"(a[3]), "r"(b[0]), "r"(b[1]));
}

// ---------------- ELL build ----------------
__global__ void k_zero(int n) {
    int i = blockIdx.x * blockDim.x + threadIdx.x;
    if (i < n) g_cursor[i] = 0;
}
__global__ void k_fill_ell(const int* __restrict__ src, const int* __restrict__ dst, int e) {
    int i = blockIdx.x * blockDim.x + threadIdx.x;
    if (i < e) {
        int d = dst[i];
        int p = atomicAdd(&g_cursor[d], 1);
        if (p < ELLW) g_adj_ell[(size_t)d * ELLW + p] = src[i];
    }
}

// ---------------- W preprocessing: m16n8k16 B-fragment order, fp16 ----------------
__global__ void k_prepw(const float* __restrict__ Ws, const float* __restrict__ Wn,
                        __half* __restrict__ o, int dout) {
    int i = blockIdx.x * blockDim.x + threadIdx.x;
    int dout2 = 2 * dout;
    if (i >= 128 * dout2) return;
    int k = i / dout2, nn = i % dout2;
    float v = (nn < dout) ? Ws[k * dout + nn] : Wn[k * dout + nn - dout];
    int NT2 = dout2 >> 3;
    int ks = k >> 4, nt = nn >> 3;
    int lane = ((nn & 7) << 2) | ((k & 7) >> 1);
    int reg = (k >> 3) & 1;
    int idx = ((((ks * NT2 + nt) * 32 + lane) * 2 + reg) << 1) | (k & 1);
    o[idx] = __float2half(v);
}

// ---------------- shared MMA mainloop + epilogue (A already in Asm) ----------------
template <int DOUT>
__device__ __forceinline__ void mma_and_store(
    const __half* Wsm, const __half* Asm, const float* __restrict__ bias,
    __half* __restrict__ ys, __half* __restrict__ z, int n, int row0,
    int wid, int lane) {
    constexpr int DOUT2 = 2 * DOUT;
    constexpr int NT2 = DOUT2 / 8;
    constexpr int NT = NT2 / 2;
    constexpr int ASTRIDE = 136;

    int wm = wid & 3, wn = wid >> 2;
    float acc[2][NT][4];
#pragma unroll
    for (int i = 0; i < 2; ++i)
#pragma unroll
        for (int j = 0; j < NT; ++j)
#pragma unroll
            for (int q = 0; q < 4; ++q) acc[i][j][q] = 0.f;

    uint32_t abase = smem_u32(Asm);
#pragma unroll
    for (int ks = 0; ks < 8; ++ks) {
        uint32_t af[2][4];
#pragma unroll
        for (int i = 0; i < 2; ++i) {
            int row = (wm * 2 + i) * 16 + (lane & 15);
            int col = ks * 16 + (lane >> 4) * 8;
            ldmatrix_x4(af[i], abase + (row * ASTRIDE + col) * 2);
        }
#pragma unroll
        for (int nt = 0; nt < NT; ++nt) {
            int ntg = wn * NT + nt;
            uint2 b2 = *(const uint2*)(Wsm + ((ks * NT2 + ntg) * 32 + lane) * 4);
            uint32_t bf[2] = {b2.x, b2.y};
            mma16(acc[0][nt], af[0], bf);
            mma16(acc[1][nt], af[1], bf);
        }
    }

    int gp = lane >> 2, tg = lane & 3;
#pragma unroll
    for (int i = 0; i < 2; ++i) {
        int r = row0 + (wm * 2 + i) * 16 + gp;
#pragma unroll
        for (int nt = 0; nt < NT; ++nt) {
            int cc = (wn * NT + nt) * 8 + tg * 2;
            if (wn == 0) {
                float b0 = bias[cc], b1 = bias[cc + 1];
                __half2 p0 = __floats2half2_rn(acc[i][nt][0] + b0, acc[i][nt][1] + b1);
                __half2 p1 = __floats2half2_rn(acc[i][nt][2] + b0, acc[i][nt][3] + b1);
                if (r < n)     *(__half2*)(ys + (size_t)r * DOUT + cc) = p0;
                if (r + 8 < n) *(__half2*)(ys + (size_t)(r + 8) * DOUT + cc) = p1;
            } else {
                int c2 = cc - DOUT;
                __half2 p0 = __floats2half2_rn(acc[i][nt][0], acc[i][nt][1]);
                __half2 p1 = __floats2half2_rn(acc[i][nt][2], acc[i][nt][3]);
                if (r < n)     *(__half2*)(z + (size_t)r * DOUT + c2) = p0;
                if (r + 8 < n) *(__half2*)(z + (size_t)(r + 8) * DOUT + c2) = p1;
            }
        }
    }
}

// ---------------- layer-0 GEMM: persistent tiles, pipelined A from fp32 x ----------------
__global__ __launch_bounds__(256, 1)
void k_gemm_f32(const float* __restrict__ X, const __half* __restrict__ Wimg,
                const float* __restrict__ bias, __half* __restrict__ ys,
                __half* __restrict__ z, int n, int ntiles) {
    constexpr int DOUT = 128;
    constexpr int DOUT2 = 256;
    constexpr int ASTRIDE = 136;
    extern __shared__ __half smh[];
    __half* Wsm = smh;
    __half* Asm = smh + 128 * DOUT2;
    int tid = threadIdx.x, wid = tid >> 5, lane = tid & 31;

    {
        const uint4* g = (const uint4*)Wimg;
        uint4* s = (uint4*)Wsm;
        for (int i = tid; i < 128 * DOUT2 / 8; i += 256) s[i] = g[i];
    }

    auto ldg_tile = [&](int t, uint4* v) {
        int row0 = t * 128;
#pragma unroll
        for (int u = 0; u < 8; ++u) {
            int idx = tid + u * 256;
            int r = idx >> 4, c8 = idx & 15;
            int gr = row0 + r;
            uint4 o = {0u, 0u, 0u, 0u};
            if (gr < n) {
                const float4* xr = (const float4*)(X + (size_t)gr * 128 + c8 * 8);
                float4 v0 = xr[0], v1 = xr[1];
                __half2 h0 = __floats2half2_rn(v0.x, v0.y);
                __half2 h1 = __floats2half2_rn(v0.z, v0.w);
                __half2 h2 = __floats2half2_rn(v1.x, v1.y);
                __half2 h3 = __floats2half2_rn(v1.z, v1.w);
                o.x = *(uint32_t*)&h0; o.y = *(uint32_t*)&h1;
                o.z = *(uint32_t*)&h2; o.w = *(uint32_t*)&h3;
            }
            v[u] = o;
        }
    };

    uint4 v[8];
    int t = blockIdx.x;
    if (t < ntiles) ldg_tile(t, v);
    for (; t < ntiles; t += gridDim.x) {
#pragma unroll
        for (int u = 0; u < 8; ++u) {
            int idx = tid + u * 256;
            int r = idx >> 4, c8 = idx & 15;
            *(uint4*)(Asm + r * ASTRIDE + c8 * 8) = v[u];
        }
        __syncthreads();
        int tn = t + gridDim.x;
        if (tn < ntiles) ldg_tile(tn, v);   // overlaps MMA below
        mma_and_store<DOUT>(Wsm, Asm, bias, ys, z, n, t * 128, wid, lane);
        __syncthreads();
    }
}

// ---------------- layers 1/2 GEMM: persistent tiles, pipelined A from fp16 ----------------
template <int DOUT>
__global__ __launch_bounds__(256, 1)
void k_gemm(const __half* __restrict__ A, const __half* __restrict__ Wimg,
            const float* __restrict__ bias, __half* __restrict__ ys,
            __half* __restrict__ z, int n, int ntiles) {
    constexpr int DOUT2 = 2 * DOUT;
    constexpr int ASTRIDE = 136;
    extern __shared__ __half smh[];
    __half* Wsm = smh;
    __half* Asm = smh + 128 * DOUT2;
    int tid = threadIdx.x, wid = tid >> 5, lane = tid & 31;

    {
        const uint4* g = (const uint4*)Wimg;
        uint4* s = (uint4*)Wsm;
        for (int i = tid; i < 128 * DOUT2 / 8; i += 256) s[i] = g[i];
    }

    const uint2* g = (const uint2*)A;
    auto ldg_tile = [&](int t, uint2* v) {
        int row0 = t * 128;
#pragma unroll
        for (int u = 0; u < 16; ++u) {
            int idx = tid + u * 256;
            int r = idx >> 5, c = idx & 31;
            int gr = row0 + r;
            uint2 tt = {0u, 0u};
            if (gr < n) tt = g[(size_t)gr * 32 + c];
            v[u] = tt;
        }
    };

    uint2 v[16];
    int t = blockIdx.x;
    if (t < ntiles) ldg_tile(t, v);
    for (; t < ntiles; t += gridDim.x) {
#pragma unroll
        for (int u = 0; u < 16; ++u) {
            int idx = tid + u * 256;
            int r = idx >> 5, c = idx & 31;
            *(uint2*)(Asm + r * ASTRIDE + c * 4) = v[u];
        }
        __syncthreads();
        int tn = t + gridDim.x;
        if (tn < ntiles) ldg_tile(tn, v);   // overlaps MMA below
        mma_and_store<DOUT>(Wsm, Asm, bias, ys, z, n, t * 128, wid, lane);
        __syncthreads();
    }
}

// ---------------- combine: persistent grid-stride, warp per node ----------------
template <int DOUT, bool RELU, typename OutT>
__global__ __launch_bounds__(512)
void k_comb(const __half* __restrict__ z, const __half* __restrict__ ys,
            OutT* __restrict__ out, int n) {
    int lane = threadIdx.x & 31;
    int wid = threadIdx.x >> 5;
    int wstride = gridDim.x * 16;

    for (int nid = blockIdx.x * 16 + wid; nid < n; nid += wstride) {
        int deg = g_cursor[nid];
        if (deg > ELLW) deg = ELLW;
        float di = 1.0f / (float)max(deg, 1);
        const int* row = g_adj_ell + (size_t)nid * ELLW;

        if constexpr (DOUT == 128) {
            const uint2* z2 = (const uint2*)z;
            uint2 yv = __ldg((const uint2*)ys + (size_t)nid * 32 + lane);
            float a0 = 0.f, a1 = 0.f, a2 = 0.f, a3 = 0.f;
            int j = 0;
            for (; j + 7 < deg; j += 8) {
                uint2 t[8];
#pragma unroll
                for (int u = 0; u < 8; ++u) t[u] = __ldg(z2 + (size_t)row[j + u] * 32 + lane);
#pragma unroll
                for (int u = 0; u < 8; ++u) {
                    float2 fl = __half22float2(*(const __half2*)&t[u].x);
                    float2 fh = __half22float2(*(const __half2*)&t[u].y);
                    a0 += fl.x; a1 += fl.y; a2 += fh.x; a3 += fh.y;
                }
            }
            for (; j < deg; ++j) {
                uint2 t = __ldg(z2 + (size_t)row[j] * 32 + lane);
                float2 fl = __half22float2(*(const __half2*)&t.x);
                float2 fh = __half22float2(*(const __half2*)&t.y);
                a0 += fl.x; a1 += fl.y; a2 += fh.x; a3 += fh.y;
            }
            float2 yl = __half22float2(*(const __half2*)&yv.x);
            float2 yh = __half22float2(*(const __half2*)&yv.y);
            float f0 = a0 * di + yl.x, f1 = a1 * di + yl.y;
            float f2 = a2 * di + yh.x, f3 = a3 * di + yh.y;
            if (RELU) {
                f0 = fmaxf(f0, 0.f); f1 = fmaxf(f1, 0.f);
                f2 = fmaxf(f2, 0.f); f3 = fmaxf(f3, 0.f);
            }
            __half2 lo = __floats2half2_rn(f0, f1);
            __half2 hi = __floats2half2_rn(f2, f3);
            uint2 o;
            o.x = *(uint32_t*)&lo;
            o.y = *(uint32_t*)&hi;
            ((uint2*)out)[(size_t)nid * 32 + lane] = o;
        } else {
            const uint32_t* z1 = (const uint32_t*)z;
            uint32_t yv = __ldg((const uint32_t*)ys + (size_t)nid * 32 + lane);
            float a0 = 0.f, a1 = 0.f;
            int j = 0;
            for (; j + 7 < deg; j += 8) {
                uint32_t t[8];
#pragma unroll
                for (int u = 0; u < 8; ++u) t[u] = __ldg(z1 + (size_t)row[j + u] * 32 + lane);
#pragma unroll
                for (int u = 0; u < 8; ++u) {
                    float2 f = __half22float2(*(const __half2*)&t[u]);
                    a0 += f.x; a1 += f.y;
                }
            }
            for (; j < deg; ++j) {
                uint32_t t = __ldg(z1 + (size_t)row[j] * 32 + lane);
                float2 f = __half22float2(*(const __half2*)&t);
                a0 += f.x; a1 += f.y;
            }
            float2 yf = __half22float2(*(const __half2*)&yv);
            float2 o;
            o.x = a0 * di + yf.x;
            o.y = a1 * di + yf.y;
            if (RELU) { o.x = fmaxf(o.x, 0.f); o.y = fmaxf(o.y, 0.f); }
            ((float2*)out)[(size_t)nid * 32 + lane] = o;
        }
    }
}

// ---------------- launch ----------------
extern "C" void kernel_launch(void* const* d_in, const int* in_sizes, int n_in,
                              void* d_out, int out_size) {
    const float* x   = (const float*)d_in[0];
    const int*   src = (const int*)d_in[1];
    const int*   dst = (const int*)d_in[2];
    const float* Ws0 = (const float*)d_in[3];
    const float* Wn0 = (const float*)d_in[4];
    const float* b0  = (const float*)d_in[5];
    const float* Ws1 = (const float*)d_in[6];
    const float* Wn1 = (const float*)d_in[7];
    const float* b1  = (const float*)d_in[8];
    const float* Ws2 = (const float*)d_in[9];
    const float* Wn2 = (const float*)d_in[10];
    const float* b2  = (const float*)d_in[11];
    float* out = (float*)d_out;

    int n = in_sizes[0] / 128;
    int e = in_sizes[1];

    __half *hA, *hB, *ys, *z, *wt0, *wt1, *wt2;
    cudaGetSymbolAddress((void**)&hA,  g_hA);
    cudaGetSymbolAddress((void**)&hB,  g_hB);
    cudaGetSymbolAddress((void**)&ys,  g_ys);
    cudaGetSymbolAddress((void**)&z,   g_z);
    cudaGetSymbolAddress((void**)&wt0, g_wt0);
    cudaGetSymbolAddress((void**)&wt1, g_wt1);
    cudaGetSymbolAddress((void**)&wt2, g_wt2);

    const int SM128 = (128 * 256 + 128 * 136) * 2;   // 100352
    const int SM64  = (128 * 128 + 128 * 136) * 2;   // 67584
    cudaFuncSetAttribute(k_gemm_f32,
                         cudaFuncAttributeMaxDynamicSharedMemorySize, SM128);
    cudaFuncSetAttribute(k_gemm<128>,
                         cudaFuncAttributeMaxDynamicSharedMemorySize, SM128);
    cudaFuncSetAttribute(k_gemm<64>,
                         cudaFuncAttributeMaxDynamicSharedMemorySize, SM64);

    int nsm = 148;
    cudaDeviceGetAttribute(&nsm, cudaDevAttrMultiProcessorCount, 0);

    int ntiles = (n + 127) / 128;
    int gp = 2 * nsm;                 // persistent gemm grid (2 CTAs/SM)
    if (gp > ntiles) gp = ntiles;
    int gc = 4 * nsm;                 // persistent comb grid (4 x 512thr / SM)

    cudaStream_t s2;
    cudaStreamCreateWithFlags(&s2, cudaStreamNonBlocking);
    cudaEvent_t evFork, evJoin1, evJoin2;
    cudaEventCreateWithFlags(&evFork, cudaEventDisableTiming);
    cudaEventCreateWithFlags(&evJoin1, cudaEventDisableTiming);
    cudaEventCreateWithFlags(&evJoin2, cudaEventDisableTiming);

    // (1) main: wt0 prep
    k_prepw<<<(128 * 256 + 255) / 256, 256>>>(Ws0, Wn0, wt0, 128);

    cudaEventRecord(evFork, 0);
    cudaStreamWaitEvent(s2, evFork, 0);

    // s2: ELL build + wt1 prep
    k_zero<<<(n + 255) / 256, 256, 0, s2>>>(n);
    k_fill_ell<<<(e + 255) / 256, 256, 0, s2>>>(src, dst, e);
    k_prepw<<<(128 * 256 + 255) / 256, 256, 0, s2>>>(Ws1, Wn1, wt1, 128);
    cudaEventRecord(evJoin1, s2);

    // main: gemm0
    k_gemm_f32<<<gp, 256, SM128>>>(x, wt0, b0, ys, z, n, ntiles);

    cudaStreamWaitEvent(0, evJoin1, 0);

    k_comb<128, true, __half><<<gc, 512>>>(z, ys, hA, n);

    // s2: wt2 prep (hidden)
    k_prepw<<<(128 * 128 + 255) / 256, 256, 0, s2>>>(Ws2, Wn2, wt2, 64);
    cudaEventRecord(evJoin2, s2);

    k_gemm<128><<<gp, 256, SM128>>>(hA, wt1, b1, ys, z, n, ntiles);
    k_comb<128, true, __half><<<gc, 512>>>(z, ys, hB, n);

    cudaStreamWaitEvent(0, evJoin2, 0);
    k_gemm<64><<<gp, 256, SM64>>>(hB, wt2, b2, ys, z, n, ntiles);
    k_comb<64, false, float><<<gc, 512>>>(z, ys, out, n);

    cudaEventDestroy(evFork);
    cudaEventDestroy(evJoin1);
    cudaEventDestroy(evJoin2);
    cudaStreamDestroy(s2);
}